// round 7
// baseline (speedup 1.0000x reference)
#include <cuda_runtime.h>
#include <cstdint>

#define BATCH 8
#define CDIM 64
#define NDIM 110592                 // 48*48*48
#define CN (CDIM*NDIM)

#define CHUNK 1024
#define NCHK (NDIM/CHUNK)           // 108
#define GBLOCKS (BATCH*NCHK)        // 864
#define NIT (CHUNK/64)              // 16

#define TILE3 1024
#define SUB 64
#define NSUB (TILE3/SUB)            // 16

// scratch (no cudaMalloc allowed)
__device__ float    g_partial[GBLOCKS][CDIM*CDIM];   // 14.2 MB
__device__ uint32_t g_affp[BATCH][CDIM*32];          // packed bf16-pair affinity [c][pd]

__device__ __forceinline__ uint32_t packbf(float lo, float hi) {
    uint32_t r;   // PTX operand order: d, a(hi), b(lo)
    asm("cvt.rn.satfinite.bf16x2.f32 %0, %1, %2;" : "=r"(r) : "f"(hi), "f"(lo));
    return r;
}

__device__ __forceinline__ void mma_bf16(float* d,
                                         uint32_t a0, uint32_t a1, uint32_t a2, uint32_t a3,
                                         uint32_t b0, uint32_t b1) {
    asm volatile("mma.sync.aligned.m16n8k16.row.col.f32.bf16.bf16.f32 "
                 "{%0,%1,%2,%3}, {%4,%5,%6,%7}, {%8,%9}, {%0,%1,%2,%3};"
                 : "+f"(d[0]), "+f"(d[1]), "+f"(d[2]), "+f"(d[3])
                 : "r"(a0), "r"(a1), "r"(a2), "r"(a3), "r"(b0), "r"(b1));
}

// ---------------------------------------------------------------------------
// Pass 1: partial Gram, bf16 m16n8k16. Prefetch distance 2, ONE sync/iter.
// ---------------------------------------------------------------------------
__global__ __launch_bounds__(256) void gram_kernel(const float* __restrict__ x) {
    int b = blockIdx.x / NCHK;
    int chunk = blockIdx.x % NCHK;
    const float* xb = x + (size_t)b * CN + (size_t)chunk * CHUNK;

    __shared__ uint32_t tile[2][CDIM][36];

    int tid = threadIdx.x;
    int lane = tid & 31, warp = tid >> 5;
    int gid = lane >> 2, tg = lane & 3;
    int m0 = (warp & 3) * 16;
    int n0 = (warp >> 2) * 32;

    int lrow = tid >> 2;
    int cb = (tid & 3) * 4;
    const float* rowp = xb + (size_t)lrow * NDIM + cb;
    int pbase = (tid & 3) * 2;

    float acc[4][4];
#pragma unroll
    for (int t = 0; t < 4; t++)
#pragma unroll
        for (int i = 0; i < 4; i++) acc[t][i] = 0.f;

    float4 v[2][4];
    // preload it0, it1
#pragma unroll
    for (int i = 0; i < 4; i++) v[0][i] = *(const float4*)(rowp + 16 * i);
#pragma unroll
    for (int i = 0; i < 4; i++) v[1][i] = *(const float4*)(rowp + 64 + 16 * i);
    // pack it0 -> tile[0]
#pragma unroll
    for (int i = 0; i < 4; i++) {
        uint32_t p0 = packbf(v[0][i].x, v[0][i].y);
        uint32_t p1 = packbf(v[0][i].z, v[0][i].w);
        *(uint2*)&tile[0][lrow][pbase + 8 * i] = make_uint2(p0, p1);
    }
    __syncthreads();

#pragma unroll 2
    for (int it = 0; it < NIT; it++) {
        int p = it & 1;
        // load it+2 into vbuf[p] (its old data already packed)
        if (it + 2 < NIT) {
            const float* src = rowp + (it + 2) * 64;
#pragma unroll
            for (int i = 0; i < 4; i++) v[p][i] = *(const float4*)(src + 16 * i);
        }
        // compute on tile[p]
        {
            const uint32_t (*T)[36] = tile[p];
#pragma unroll
            for (int s = 0; s < 4; s++) {
                int pa = 8 * s + tg;
                uint32_t a0 = T[m0 + gid][pa];
                uint32_t a1 = T[m0 + 8 + gid][pa];
                uint32_t a2 = T[m0 + gid][pa + 4];
                uint32_t a3 = T[m0 + 8 + gid][pa + 4];
#pragma unroll
                for (int t = 0; t < 4; t++) {
                    uint32_t b0 = T[n0 + t * 8 + gid][pa];
                    uint32_t b1 = T[n0 + t * 8 + gid][pa + 4];
                    mma_bf16(acc[t], a0, a1, a2, a3, b0, b1);
                }
            }
        }
        // pack it+1 (vbuf[p^1]) -> tile[p^1]
        if (it + 1 < NIT) {
#pragma unroll
            for (int i = 0; i < 4; i++) {
                uint32_t p0 = packbf(v[p ^ 1][i].x, v[p ^ 1][i].y);
                uint32_t p1 = packbf(v[p ^ 1][i].z, v[p ^ 1][i].w);
                *(uint2*)&tile[p ^ 1][lrow][pbase + 8 * i] = make_uint2(p0, p1);
            }
        }
        __syncthreads();
    }

    float* gp = g_partial[blockIdx.x];
#pragma unroll
    for (int t = 0; t < 4; t++) {
        int cc = n0 + t * 8 + tg * 2;
        gp[(m0 + gid) * CDIM + cc]         = acc[t][0];
        gp[(m0 + gid) * CDIM + cc + 1]     = acc[t][1];
        gp[(m0 + 8 + gid) * CDIM + cc]     = acc[t][2];
        gp[(m0 + 8 + gid) * CDIM + cc + 1] = acc[t][3];
    }
}

// ---------------------------------------------------------------------------
// Pass 2: reduce partials -> G, m3 = G@G, affinity = sigmoid(m3),
// emitted PRE-PACKED as bf16 pairs along d: g_affp[b][c][pd].
// ---------------------------------------------------------------------------
__global__ __launch_bounds__(256) void affinity_kernel() {
    int b = blockIdx.x;
    __shared__ float Gs[CDIM][CDIM + 1];
    int tid = threadIdx.x;

    float s[16];
#pragma unroll
    for (int u = 0; u < 16; u++) s[u] = 0.f;
    for (int j = 0; j < NCHK; j++) {
        const float* gp = g_partial[b * NCHK + j];
#pragma unroll
        for (int u = 0; u < 16; u++) s[u] += gp[tid + 256 * u];
    }
#pragma unroll
    for (int u = 0; u < 16; u++) {
        int idx = tid + 256 * u;
        Gs[idx >> 6][idx & 63] = s[u];
    }
    __syncthreads();

    int r = tid >> 2;
    int c0 = (tid & 3) * 16;
    float vals[16];
#pragma unroll
    for (int j = 0; j < 16; j++) {
        float acc = 0.f;
#pragma unroll 8
        for (int d = 0; d < CDIM; d++)
            acc += Gs[r][d] * Gs[d][c0 + j];
        vals[j] = 1.f / (1.f + expf(-acc));
    }
    uint32_t pw[8];
#pragma unroll
    for (int j = 0; j < 8; j++) pw[j] = packbf(vals[2 * j], vals[2 * j + 1]);
    uint32_t* dst = &g_affp[b][r * 32 + (tid & 3) * 8];
    *(uint4*)(dst)     = make_uint4(pw[0], pw[1], pw[2], pw[3]);
    *(uint4*)(dst + 4) = make_uint4(pw[4], pw[5], pw[6], pw[7]);
}

// ---------------------------------------------------------------------------
// Pass 3: out = gamma * (Aff @ K) + x.  bf16 m16n8k16, m32 x n16 per warp.
// Double-buffered P tile, prefetch distance 2, ONE sync/iter.
// Addend prefetched into regs before MMA; A fragments from packed affinity.
// ---------------------------------------------------------------------------
__global__ __launch_bounds__(256) void apply_kernel(const float* __restrict__ x,
                                                    const float* __restrict__ gamma_p,
                                                    float* __restrict__ out) {
    int b = blockIdx.x / (NDIM / TILE3);
    int tblk = blockIdx.x % (NDIM / TILE3);
    size_t base = (size_t)b * CN;
    const float* xb = x + base + (size_t)tblk * TILE3;
    float* ob = out + base + (size_t)tblk * TILE3;
    float gamma = *gamma_p;

    __shared__ uint32_t P[2][32][72];   // bf16 pairs along channel d, 64 n-cols

    int tid = threadIdx.x;
    int lane = tid & 31, warp = tid >> 5;
    int gid = lane >> 2, tg = lane & 3;
    int m0 = (warp & 1) * 32;
    int n0w = (warp >> 1) * 16;

    // A fragments: 2 m-slabs x 4 k-slabs x 4 regs (L2-broadcast)
    const uint32_t* PA = g_affp[b];
    uint32_t afr[2][4][4];
#pragma unroll
    for (int mi = 0; mi < 2; mi++) {
        int mr = m0 + 16 * mi + gid;
#pragma unroll
        for (int s = 0; s < 4; s++) {
            int pa = s * 8 + tg;
            afr[mi][s][0] = PA[mr * 32 + pa];
            afr[mi][s][1] = PA[(mr + 8) * 32 + pa];
            afr[mi][s][2] = PA[mr * 32 + pa + 4];
            afr[mi][s][3] = PA[(mr + 8) * 32 + pa + 4];
        }
    }

    // loader role: pair-row pr (rows 2pr,2pr+1), 8 cols at cg*8
    int pr = tid >> 3;
    int cg = tid & 7;
    const float* row0 = xb + (size_t)(2 * pr) * NDIM + cg * 8;
    const float* row1 = row0 + NDIM;

    float4 v[2][4];                     // [buf][u0,u1,w0,w1]
    v[0][0] = *(const float4*)(row0);
    v[0][1] = *(const float4*)(row0 + 4);
    v[0][2] = *(const float4*)(row1);
    v[0][3] = *(const float4*)(row1 + 4);
    v[1][0] = *(const float4*)(row0 + SUB);
    v[1][1] = *(const float4*)(row0 + SUB + 4);
    v[1][2] = *(const float4*)(row1 + SUB);
    v[1][3] = *(const float4*)(row1 + SUB + 4);
    {
        uint4 p0 = make_uint4(packbf(v[0][0].x, v[0][2].x), packbf(v[0][0].y, v[0][2].y),
                              packbf(v[0][0].z, v[0][2].z), packbf(v[0][0].w, v[0][2].w));
        uint4 p1 = make_uint4(packbf(v[0][1].x, v[0][3].x), packbf(v[0][1].y, v[0][3].y),
                              packbf(v[0][1].z, v[0][3].z), packbf(v[0][1].w, v[0][3].w));
        *(uint4*)&P[0][pr][cg * 8]     = p0;
        *(uint4*)&P[0][pr][cg * 8 + 4] = p1;
    }
    __syncthreads();

#pragma unroll 2
    for (int sub = 0; sub < NSUB; sub++) {
        int p = sub & 1;
        int nbase = sub * SUB;

        // (1) load sub+2 into vbuf[p]
        if (sub + 2 < NSUB) {
            const float* s0 = row0 + (sub + 2) * SUB;
            const float* s1 = row1 + (sub + 2) * SUB;
            v[p][0] = *(const float4*)(s0);
            v[p][1] = *(const float4*)(s0 + 4);
            v[p][2] = *(const float4*)(s1);
            v[p][3] = *(const float4*)(s1 + 4);
        }

        // (2) prefetch this sub's f32 addend into regs
        float2 xadd[2][2][2];           // [mi][half][t]
#pragma unroll
        for (int mi = 0; mi < 2; mi++)
#pragma unroll
            for (int h = 0; h < 2; h++) {
                int r = m0 + 16 * mi + 8 * h + gid;
#pragma unroll
                for (int t = 0; t < 2; t++) {
                    int cc = nbase + n0w + t * 8 + tg * 2;
                    xadd[mi][h][t] = *(const float2*)(xb + (size_t)r * NDIM + cc);
                }
            }

        // (3) MMA on P[p]
        float acc[2][2][4];
#pragma unroll
        for (int mi = 0; mi < 2; mi++)
#pragma unroll
            for (int t = 0; t < 2; t++)
#pragma unroll
                for (int i = 0; i < 4; i++) acc[mi][t][i] = 0.f;

#pragma unroll
        for (int s = 0; s < 4; s++) {
            int pa = s * 8 + tg;
#pragma unroll
            for (int t = 0; t < 2; t++) {
                int n = n0w + t * 8 + gid;
                uint32_t b0 = P[p][pa][n];
                uint32_t b1 = P[p][pa + 4][n];
                mma_bf16(acc[0][t], afr[0][s][0], afr[0][s][1], afr[0][s][2], afr[0][s][3], b0, b1);
                mma_bf16(acc[1][t], afr[1][s][0], afr[1][s][1], afr[1][s][2], afr[1][s][3], b0, b1);
            }
        }

        // (4) epilogue
#pragma unroll
        for (int mi = 0; mi < 2; mi++)
#pragma unroll
            for (int t = 0; t < 2; t++) {
                int cc = nbase + n0w + t * 8 + tg * 2;
                int r0 = m0 + 16 * mi + gid, r1 = r0 + 8;
                float2 o0 = make_float2(fmaf(gamma, acc[mi][t][0], xadd[mi][0][t].x),
                                        fmaf(gamma, acc[mi][t][1], xadd[mi][0][t].y));
                float2 o1 = make_float2(fmaf(gamma, acc[mi][t][2], xadd[mi][1][t].x),
                                        fmaf(gamma, acc[mi][t][3], xadd[mi][1][t].y));
                *(float2*)(ob + (size_t)r0 * NDIM + cc) = o0;
                *(float2*)(ob + (size_t)r1 * NDIM + cc) = o1;
            }

        // (5) pack sub+1 (vbuf[p^1]) -> P[p^1]
        if (sub + 1 < NSUB) {
            uint4 p0 = make_uint4(packbf(v[p^1][0].x, v[p^1][2].x), packbf(v[p^1][0].y, v[p^1][2].y),
                                  packbf(v[p^1][0].z, v[p^1][2].z), packbf(v[p^1][0].w, v[p^1][2].w));
            uint4 p1 = make_uint4(packbf(v[p^1][1].x, v[p^1][3].x), packbf(v[p^1][1].y, v[p^1][3].y),
                                  packbf(v[p^1][1].z, v[p^1][3].z), packbf(v[p^1][1].w, v[p^1][3].w));
            *(uint4*)&P[p ^ 1][pr][cg * 8]     = p0;
            *(uint4*)&P[p ^ 1][pr][cg * 8 + 4] = p1;
        }
        __syncthreads();
    }
}

extern "C" void kernel_launch(void* const* d_in, const int* in_sizes, int n_in,
                              void* d_out, int out_size) {
    (void)in_sizes; (void)n_in; (void)out_size;
    const float* x = (const float*)d_in[0];
    const float* gamma = (const float*)d_in[1];
    float* out = (float*)d_out;

    gram_kernel<<<GBLOCKS, 256>>>(x);
    affinity_kernel<<<BATCH, 256>>>();
    apply_kernel<<<BATCH * (NDIM / TILE3), 256>>>(x, gamma, out);
}

// round 8
// speedup vs baseline: 1.2346x; 1.2346x over previous
#include <cuda_runtime.h>
#include <cstdint>

#define BATCH 8
#define CDIM 64
#define NDIM 110592                 // 48*48*48
#define CN (CDIM*NDIM)

#define CHUNK 2048
#define NCHK (NDIM/CHUNK)           // 54
#define GBLOCKS (BATCH*NCHK)        // 432
#define NIT (CHUNK/64)              // 32

#define TILE3 1024
#define SUB 64
#define NSUB (TILE3/SUB)            // 16

// scratch (no cudaMalloc allowed)
__device__ float    g_partial[GBLOCKS][CDIM*CDIM];   // 7.08 MB
__device__ uint32_t g_affp[BATCH][CDIM*32];          // packed bf16-pair affinity [c][pd]

__device__ __forceinline__ uint32_t packbf(float lo, float hi) {
    uint32_t r;   // PTX operand order: d, a(hi), b(lo)
    asm("cvt.rn.satfinite.bf16x2.f32 %0, %1, %2;" : "=r"(r) : "f"(hi), "f"(lo));
    return r;
}

__device__ __forceinline__ void mma_bf16(float* d, const uint32_t* a,
                                         uint32_t b0, uint32_t b1) {
    asm volatile("mma.sync.aligned.m16n8k16.row.col.f32.bf16.bf16.f32 "
                 "{%0,%1,%2,%3}, {%4,%5,%6,%7}, {%8,%9}, {%0,%1,%2,%3};"
                 : "+f"(d[0]), "+f"(d[1]), "+f"(d[2]), "+f"(d[3])
                 : "r"(a[0]), "r"(a[1]), "r"(a[2]), "r"(a[3]), "r"(b0), "r"(b1));
}

__device__ __forceinline__ void ldsm_x4(uint32_t* r, uint32_t addr) {
    asm volatile("ldmatrix.sync.aligned.m8n8.x4.shared.b16 {%0,%1,%2,%3}, [%4];"
                 : "=r"(r[0]), "=r"(r[1]), "=r"(r[2]), "=r"(r[3]) : "r"(addr));
}
__device__ __forceinline__ void ldsm_x4_t(uint32_t* r, uint32_t addr) {
    asm volatile("ldmatrix.sync.aligned.m8n8.x4.trans.shared.b16 {%0,%1,%2,%3}, [%4];"
                 : "=r"(r[0]), "=r"(r[1]), "=r"(r[2]), "=r"(r[3]) : "r"(addr));
}

// ---------------------------------------------------------------------------
// Pass 1: partial Gram. 8 warps = 2 k-groups x (2m x 2n) of m32n32 warp tiles.
// Coalesced loader (4 lines/LDG), ldmatrix fragment loads, cross-k reduce at end.
// ---------------------------------------------------------------------------
__global__ __launch_bounds__(256) void gram_kernel(const float* __restrict__ x) {
    int b = blockIdx.x / NCHK;
    int chunk = blockIdx.x % NCHK;
    const float* xb = x + (size_t)b * CN + (size_t)chunk * CHUNK;

    __shared__ uint32_t tile[2][CDIM][36];   // bf16 pairs along k

    int tid = threadIdx.x;
    int lane = tid & 31, warp = tid >> 5;
    int gid = lane >> 2, tg = lane & 3;
    int kg = warp >> 2;                      // k-group 0/1
    int m0 = ((warp >> 1) & 1) * 32;
    int n0 = (warp & 1) * 32;

    // coalesced loader: rows r16+16j, 16 consecutive floats each
    int r16 = tid >> 4;                      // 0..15
    int c16 = tid & 15;                      // 0..15
    const float* rowp = xb + (size_t)r16 * NDIM + c16 * 4;

    // ldmatrix byte offsets (within one tile buffer); col unit = 4B pair
    int arow = (lane & 7) + ((lane >> 3) & 1) * 8;
    int acol = ((lane >> 4) & 1) * 4;
    int brow = (lane & 7) + ((lane >> 4) & 1) * 8;
    int bcol = ((lane >> 3) & 1) * 4;
    uint32_t base0 = (uint32_t)__cvta_generic_to_shared(&tile[0][0][0]);
    uint32_t base1 = (uint32_t)__cvta_generic_to_shared(&tile[1][0][0]);
    uint32_t offA0 = ((m0 + arow) * 36 + acol) * 4;
    uint32_t offA1 = ((m0 + 16 + arow) * 36 + acol) * 4;
    uint32_t offB0 = ((n0 + brow) * 36 + bcol) * 4;
    uint32_t offB1 = ((n0 + 16 + brow) * 36 + bcol) * 4;
    uint32_t kgoff = (uint32_t)(kg * 16 * 4);      // 8 pairs per s-slab, 2 slabs per group

    float acc[2][4][4];
#pragma unroll
    for (int mi = 0; mi < 2; mi++)
#pragma unroll
        for (int t = 0; t < 4; t++)
#pragma unroll
            for (int i = 0; i < 4; i++) acc[mi][t][i] = 0.f;

    float4 v[2][4];
#pragma unroll
    for (int j = 0; j < 4; j++) v[0][j] = *(const float4*)(rowp + (size_t)(16 * j) * NDIM);
#pragma unroll
    for (int j = 0; j < 4; j++) v[1][j] = *(const float4*)(rowp + (size_t)(16 * j) * NDIM + 64);
#pragma unroll
    for (int j = 0; j < 4; j++) {
        uint32_t p0 = packbf(v[0][j].x, v[0][j].y);
        uint32_t p1 = packbf(v[0][j].z, v[0][j].w);
        *(uint2*)&tile[0][r16 + 16 * j][2 * c16] = make_uint2(p0, p1);
    }
    __syncthreads();

    for (int it = 0; it < NIT; it++) {
        int p = it & 1;
        if (it + 2 < NIT) {
            const float* src = rowp + (it + 2) * 64;
#pragma unroll
            for (int j = 0; j < 4; j++) v[p][j] = *(const float4*)(src + (size_t)(16 * j) * NDIM);
        }
        uint32_t baseP = p ? base1 : base0;
#pragma unroll
        for (int s = 0; s < 2; s++) {
            uint32_t co = kgoff + s * 32;
            uint32_t a0[4], a1[4], bA[4], bB[4];
            ldsm_x4(a0, baseP + offA0 + co);
            ldsm_x4(a1, baseP + offA1 + co);
            ldsm_x4(bA, baseP + offB0 + co);   // {b0t0,b1t0,b0t1,b1t1}
            ldsm_x4(bB, baseP + offB1 + co);   // {b0t2,b1t2,b0t3,b1t3}
            mma_bf16(acc[0][0], a0, bA[0], bA[1]);
            mma_bf16(acc[0][1], a0, bA[2], bA[3]);
            mma_bf16(acc[0][2], a0, bB[0], bB[1]);
            mma_bf16(acc[0][3], a0, bB[2], bB[3]);
            mma_bf16(acc[1][0], a1, bA[0], bA[1]);
            mma_bf16(acc[1][1], a1, bA[2], bA[3]);
            mma_bf16(acc[1][2], a1, bB[0], bB[1]);
            mma_bf16(acc[1][3], a1, bB[2], bB[3]);
        }
        if (it + 1 < NIT) {
#pragma unroll
            for (int j = 0; j < 4; j++) {
                uint32_t p0 = packbf(v[p ^ 1][j].x, v[p ^ 1][j].y);
                uint32_t p1 = packbf(v[p ^ 1][j].z, v[p ^ 1][j].w);
                *(uint2*)&tile[p ^ 1][r16 + 16 * j][2 * c16] = make_uint2(p0, p1);
            }
        }
        __syncthreads();
    }

    // cross-k-group reduce: kg1 warps dump accs into smem (reuse tile), kg0 add.
    float* red = (float*)&tile[0][0][0];     // 4 warps * 32 lanes * 32 floats = 16KB <= 18KB
    if (kg == 1) {
        float* dst = red + ((warp & 3) * 32 + lane) * 32;
#pragma unroll
        for (int mi = 0; mi < 2; mi++)
#pragma unroll
            for (int t = 0; t < 4; t++)
#pragma unroll
                for (int i = 0; i < 4; i++) dst[mi * 16 + t * 4 + i] = acc[mi][t][i];
    }
    __syncthreads();
    if (kg == 0) {
        const float* src = red + ((warp & 3) * 32 + lane) * 32;
        float* gp = g_partial[blockIdx.x];
#pragma unroll
        for (int mi = 0; mi < 2; mi++)
#pragma unroll
            for (int t = 0; t < 4; t++) {
                float a0 = acc[mi][t][0] + src[mi * 16 + t * 4 + 0];
                float a1 = acc[mi][t][1] + src[mi * 16 + t * 4 + 1];
                float a2 = acc[mi][t][2] + src[mi * 16 + t * 4 + 2];
                float a3 = acc[mi][t][3] + src[mi * 16 + t * 4 + 3];
                int r0 = m0 + 16 * mi + gid;
                int cc = n0 + 8 * t + 2 * tg;
                gp[r0 * CDIM + cc]           = a0;
                gp[r0 * CDIM + cc + 1]       = a1;
                gp[(r0 + 8) * CDIM + cc]     = a2;
                gp[(r0 + 8) * CDIM + cc + 1] = a3;
            }
    }
}

// ---------------------------------------------------------------------------
// Pass 2: reduce partials -> G, m3 = G@G, affinity = sigmoid(m3),
// emitted PRE-PACKED as bf16 pairs along d: g_affp[b][c][pd].
// ---------------------------------------------------------------------------
__global__ __launch_bounds__(256) void affinity_kernel() {
    int b = blockIdx.x;
    __shared__ float Gs[CDIM][CDIM + 1];
    int tid = threadIdx.x;

    float s[16];
#pragma unroll
    for (int u = 0; u < 16; u++) s[u] = 0.f;
    for (int j = 0; j < NCHK; j++) {
        const float* gp = g_partial[b * NCHK + j];
#pragma unroll
        for (int u = 0; u < 16; u++) s[u] += gp[tid + 256 * u];
    }
#pragma unroll
    for (int u = 0; u < 16; u++) {
        int idx = tid + 256 * u;
        Gs[idx >> 6][idx & 63] = s[u];
    }
    __syncthreads();

    int r = tid >> 2;
    int c0 = (tid & 3) * 16;
    float vals[16];
#pragma unroll
    for (int j = 0; j < 16; j++) {
        float acc = 0.f;
#pragma unroll 8
        for (int d = 0; d < CDIM; d++)
            acc += Gs[r][d] * Gs[d][c0 + j];
        vals[j] = 1.f / (1.f + expf(-acc));
    }
    uint32_t pw[8];
#pragma unroll
    for (int j = 0; j < 8; j++) pw[j] = packbf(vals[2 * j], vals[2 * j + 1]);
    uint32_t* dst = &g_affp[b][r * 32 + (tid & 3) * 8];
    *(uint4*)(dst)     = make_uint4(pw[0], pw[1], pw[2], pw[3]);
    *(uint4*)(dst + 4) = make_uint4(pw[4], pw[5], pw[6], pw[7]);
}

// ---------------------------------------------------------------------------
// Pass 3: out = gamma * (Aff @ K) + x.
// x tile stored as plain bf16 [d][n] (pairs along n); B frags via ldmatrix.trans.
// A frags from packed affinity in gmem. Epilogue: acc -> Os smem -> coalesced
// STG.128; the f32 addend is the loader's own registers (no extra loads).
// ---------------------------------------------------------------------------
__global__ __launch_bounds__(256) void apply_kernel(const float* __restrict__ x,
                                                    const float* __restrict__ gamma_p,
                                                    float* __restrict__ out) {
    int b = blockIdx.x / (NDIM / TILE3);
    int tblk = blockIdx.x % (NDIM / TILE3);
    size_t base = (size_t)b * CN;
    const float* xb = x + base + (size_t)tblk * TILE3;
    float* ob = out + base + (size_t)tblk * TILE3;
    float gamma = *gamma_p;

    __shared__ uint32_t Tl[2][CDIM][36];     // bf16 [d][n], pairs along n
    __shared__ float Os[CDIM][68];           // f32 accumulator staging

    int tid = threadIdx.x;
    int lane = tid & 31, warp = tid >> 5;
    int gid = lane >> 2, tg = lane & 3;
    int m0 = (warp & 1) * 32;
    int n0w = (warp >> 1) * 16;

    // A fragments from packed affinity (pairs along d) — L2-broadcast LDGs
    const uint32_t* PA = g_affp[b];
    uint32_t afr[2][4][4];
#pragma unroll
    for (int mi = 0; mi < 2; mi++) {
        int mr = m0 + 16 * mi + gid;
#pragma unroll
        for (int s = 0; s < 4; s++) {
            int pa = s * 8 + tg;
            afr[mi][s][0] = PA[mr * 32 + pa];
            afr[mi][s][1] = PA[(mr + 8) * 32 + pa];
            afr[mi][s][2] = PA[mr * 32 + pa + 4];
            afr[mi][s][3] = PA[(mr + 8) * 32 + pa + 4];
        }
    }

    // coalesced loader: rows r16+16j, 16 consecutive floats
    int r16 = tid >> 4;
    int c16 = tid & 15;
    const float* rowp = xb + (size_t)r16 * NDIM + c16 * 4;

    // B ldmatrix.trans offsets: k-rows 16s + brow2, n col n0w + bnoff (b16 units)
    int brow2 = (lane & 7) + ((lane >> 3) & 1) * 8;
    int bnoff = ((lane >> 4) & 1) * 8;
    uint32_t tb0 = (uint32_t)__cvta_generic_to_shared(&Tl[0][0][0]);
    uint32_t tb1 = (uint32_t)__cvta_generic_to_shared(&Tl[1][0][0]);
    uint32_t offB = (uint32_t)(brow2 * 144 + (n0w + bnoff) * 2);

    float4 v[2][4];
#pragma unroll
    for (int j = 0; j < 4; j++) v[0][j] = *(const float4*)(rowp + (size_t)(16 * j) * NDIM);
#pragma unroll
    for (int j = 0; j < 4; j++) {
        uint32_t p0 = packbf(v[0][j].x, v[0][j].y);
        uint32_t p1 = packbf(v[0][j].z, v[0][j].w);
        *(uint2*)&Tl[0][r16 + 16 * j][2 * c16] = make_uint2(p0, p1);
    }
    __syncthreads();

    for (int sub = 0; sub < NSUB; sub++) {
        int q = sub & 1;
        int nbase = sub * SUB;

        // (1) prefetch sub+1 into the other v buffer
        if (sub + 1 < NSUB) {
            const float* src = rowp + (sub + 1) * SUB;
#pragma unroll
            for (int j = 0; j < 4; j++) v[q ^ 1][j] = *(const float4*)(src + (size_t)(16 * j) * NDIM);
        }

        // (2) MMA on Tl[q] via ldmatrix.trans B fragments
        float acc[2][2][4];
#pragma unroll
        for (int mi = 0; mi < 2; mi++)
#pragma unroll
            for (int t = 0; t < 2; t++)
#pragma unroll
                for (int i = 0; i < 4; i++) acc[mi][t][i] = 0.f;

        uint32_t baseQ = q ? tb1 : tb0;
#pragma unroll
        for (int s = 0; s < 4; s++) {
            uint32_t br[4];                   // {b0t0,b1t0,b0t1,b1t1}
            ldsm_x4_t(br, baseQ + offB + (uint32_t)(s * 16 * 144));
            mma_bf16(acc[0][0], afr[0][s], br[0], br[1]);
            mma_bf16(acc[1][0], afr[1][s], br[0], br[1]);
            mma_bf16(acc[0][1], afr[0][s], br[2], br[3]);
            mma_bf16(acc[1][1], afr[1][s], br[2], br[3]);
        }

        // (3) stage acc into Os
#pragma unroll
        for (int mi = 0; mi < 2; mi++)
#pragma unroll
            for (int t = 0; t < 2; t++) {
                int cc = n0w + t * 8 + 2 * tg;
                int r0 = m0 + 16 * mi + gid;
                *(float2*)&Os[r0][cc]     = make_float2(acc[mi][t][0], acc[mi][t][1]);
                *(float2*)&Os[r0 + 8][cc] = make_float2(acc[mi][t][2], acc[mi][t][3]);
            }
        __syncthreads();

        // (4) coalesced drain: out = gamma*Os + v[q] (addend from loader regs)
#pragma unroll
        for (int j = 0; j < 4; j++) {
            int r = r16 + 16 * j;
            float4 o = *(float4*)&Os[r][4 * c16];
            float4 xv = v[q][j];
            float4 res = make_float4(fmaf(gamma, o.x, xv.x), fmaf(gamma, o.y, xv.y),
                                     fmaf(gamma, o.z, xv.z), fmaf(gamma, o.w, xv.w));
            *(float4*)(ob + (size_t)r * NDIM + nbase + 4 * c16) = res;
        }

        // (5) pack sub+1 into Tl[q^1]
        if (sub + 1 < NSUB) {
#pragma unroll
            for (int j = 0; j < 4; j++) {
                uint32_t p0 = packbf(v[q ^ 1][j].x, v[q ^ 1][j].y);
                uint32_t p1 = packbf(v[q ^ 1][j].z, v[q ^ 1][j].w);
                *(uint2*)&Tl[q ^ 1][r16 + 16 * j][2 * c16] = make_uint2(p0, p1);
            }
        }
        __syncthreads();
    }
}

extern "C" void kernel_launch(void* const* d_in, const int* in_sizes, int n_in,
                              void* d_out, int out_size) {
    (void)in_sizes; (void)n_in; (void)out_size;
    const float* x = (const float*)d_in[0];
    const float* gamma = (const float*)d_in[1];
    float* out = (float*)d_out;

    gram_kernel<<<GBLOCKS, 256>>>(x);
    affinity_kernel<<<BATCH, 256>>>();
    apply_kernel<<<BATCH * (NDIM / TILE3), 256>>>(x, gamma, out);
}